// round 4
// baseline (speedup 1.0000x reference)
#include <cuda_runtime.h>

// Y: [16384, 2048] fp32, row-major.
// loss = sum_d | 1 - (sum_n Y[n,d]^2) / n |

#define N_ROWS        16384
#define N_COLS        2048
#define COLS4         (N_COLS / 4)          // 512 float4 per row
#define ROWS_PER_SLAB 8
#define N_SLABS       (N_ROWS / ROWS_PER_SLAB)   // 2048 slabs
#define GRID1         296                    // 148 SMs x 2 blocks, single wave

// Zero-initialized device globals (no cudaMalloc allowed).
// g_colsum accumulates per-column sum of squares via REDG; K2 re-zeroes it
// (and the steal counter) after reading, so every graph replay starts clean.
__device__ float        g_colsum[N_COLS];
__device__ unsigned int g_ctr;

__global__ __launch_bounds__(512, 2) void colsq_kernel(const float4* __restrict__ Y)
{
    const int col4 = threadIdx.x;            // 0..511, fixed column group
    float ax = 0.f, ay = 0.f, az = 0.f, aw = 0.f;

    __shared__ unsigned int s_slab;

    for (;;) {
        __syncthreads();                     // protect s_slab from prev iter readers
        if (threadIdx.x == 0) s_slab = atomicAdd(&g_ctr, 1u);
        __syncthreads();
        const unsigned int s = s_slab;
        if (s >= N_SLABS) break;

        const float4* __restrict__ p =
            Y + (size_t)s * ROWS_PER_SLAB * COLS4 + col4;

        // 8 independent LDG.128 in flight.
        float4 v0 = p[0 * COLS4];
        float4 v1 = p[1 * COLS4];
        float4 v2 = p[2 * COLS4];
        float4 v3 = p[3 * COLS4];
        float4 v4 = p[4 * COLS4];
        float4 v5 = p[5 * COLS4];
        float4 v6 = p[6 * COLS4];
        float4 v7 = p[7 * COLS4];

        ax = fmaf(v0.x, v0.x, ax); ay = fmaf(v0.y, v0.y, ay);
        az = fmaf(v0.z, v0.z, az); aw = fmaf(v0.w, v0.w, aw);
        ax = fmaf(v1.x, v1.x, ax); ay = fmaf(v1.y, v1.y, ay);
        az = fmaf(v1.z, v1.z, az); aw = fmaf(v1.w, v1.w, aw);
        ax = fmaf(v2.x, v2.x, ax); ay = fmaf(v2.y, v2.y, ay);
        az = fmaf(v2.z, v2.z, az); aw = fmaf(v2.w, v2.w, aw);
        ax = fmaf(v3.x, v3.x, ax); ay = fmaf(v3.y, v3.y, ay);
        az = fmaf(v3.z, v3.z, az); aw = fmaf(v3.w, v3.w, aw);
        ax = fmaf(v4.x, v4.x, ax); ay = fmaf(v4.y, v4.y, ay);
        az = fmaf(v4.z, v4.z, az); aw = fmaf(v4.w, v4.w, aw);
        ax = fmaf(v5.x, v5.x, ax); ay = fmaf(v5.y, v5.y, ay);
        az = fmaf(v5.z, v5.z, az); aw = fmaf(v5.w, v5.w, aw);
        ax = fmaf(v6.x, v6.x, ax); ay = fmaf(v6.y, v6.y, ay);
        az = fmaf(v6.z, v6.z, az); aw = fmaf(v6.w, v6.w, aw);
        ax = fmaf(v7.x, v7.x, ax); ay = fmaf(v7.y, v7.y, ay);
        az = fmaf(v7.z, v7.z, az); aw = fmaf(v7.w, v7.w, aw);
    }

    // One REDG.ADD per scalar column per block (296 adds/column total).
    const int c = col4 * 4;
    atomicAdd(&g_colsum[c + 0], ax);
    atomicAdd(&g_colsum[c + 1], ay);
    atomicAdd(&g_colsum[c + 2], az);
    atomicAdd(&g_colsum[c + 3], aw);
}

// Finalize: read the 2048 column sums (L2-hot), compute sum |1 - s/n|,
// write the scalar, then reset state for the next graph replay.
__global__ __launch_bounds__(512) void finalize_kernel(float* __restrict__ out)
{
    const int t = threadIdx.x;               // 0..511
    const float inv_n = 1.0f / (float)N_ROWS;

    float4 s = reinterpret_cast<const float4*>(g_colsum)[t];
    float v = fabsf(1.0f - s.x * inv_n) + fabsf(1.0f - s.y * inv_n)
            + fabsf(1.0f - s.z * inv_n) + fabsf(1.0f - s.w * inv_n);

    // Reset column sums for the next replay (each thread zeroes what it read).
    reinterpret_cast<float4*>(g_colsum)[t] = make_float4(0.f, 0.f, 0.f, 0.f);

    // Reduce 512 values -> 1.
    __shared__ float red[16];
    #pragma unroll
    for (int o = 16; o > 0; o >>= 1)
        v += __shfl_down_sync(0xffffffff, v, o);
    if ((t & 31) == 0) red[t >> 5] = v;
    __syncthreads();
    if (t < 16) {
        float x = red[t];
        #pragma unroll
        for (int o = 8; o > 0; o >>= 1)
            x += __shfl_down_sync(0xffff, x, o);
        if (t == 0) {
            out[0] = x;
            g_ctr = 0;                       // reset steal counter
        }
    }
}

extern "C" void kernel_launch(void* const* d_in, const int* in_sizes, int n_in,
                              void* d_out, int out_size)
{
    const float4* Y = (const float4*)d_in[0];
    float* out = (float*)d_out;

    colsq_kernel<<<GRID1, 512>>>(Y);
    finalize_kernel<<<1, 512>>>(out);
}

// round 5
// speedup vs baseline: 1.0060x; 1.0060x over previous
#include <cuda_runtime.h>

// Y: [16384, 2048] fp32, row-major.
// loss = sum_d | 1 - (sum_n Y[n,d]^2) / n |

#define N_ROWS        16384
#define N_COLS        2048
#define COLS4         (N_COLS / 4)               // 512 float4 per row
#define ROWS_PER_SLAB 8
#define N_SLABS       (N_ROWS / ROWS_PER_SLAB)   // 2048 slabs
#define GRID1         296                        // 148 SMs x 2 blocks, single wave

// Zero-initialized device globals (no cudaMalloc allowed). The last finishing
// block reads/resets them each launch, so every graph replay starts clean.
__device__ float        g_colsum[N_COLS];
__device__ unsigned int g_done;

__global__ __launch_bounds__(512, 2) void semidef_kernel(
    const float4* __restrict__ Y, float* __restrict__ out)
{
    const int col4 = threadIdx.x;                // 0..511, fixed column group
    float ax = 0.f, ay = 0.f, az = 0.f, aw = 0.f;

    // Static block-strided slabs: no barriers, no steal atomics in the loop.
    for (unsigned int s = blockIdx.x; s < N_SLABS; s += GRID1) {
        const float4* __restrict__ p =
            Y + (size_t)s * ROWS_PER_SLAB * COLS4 + col4;

        // 8 independent LDG.128 in flight per thread.
        float4 v0 = p[0 * COLS4];
        float4 v1 = p[1 * COLS4];
        float4 v2 = p[2 * COLS4];
        float4 v3 = p[3 * COLS4];
        float4 v4 = p[4 * COLS4];
        float4 v5 = p[5 * COLS4];
        float4 v6 = p[6 * COLS4];
        float4 v7 = p[7 * COLS4];

        ax = fmaf(v0.x, v0.x, ax); ay = fmaf(v0.y, v0.y, ay);
        az = fmaf(v0.z, v0.z, az); aw = fmaf(v0.w, v0.w, aw);
        ax = fmaf(v1.x, v1.x, ax); ay = fmaf(v1.y, v1.y, ay);
        az = fmaf(v1.z, v1.z, az); aw = fmaf(v1.w, v1.w, aw);
        ax = fmaf(v2.x, v2.x, ax); ay = fmaf(v2.y, v2.y, ay);
        az = fmaf(v2.z, v2.z, az); aw = fmaf(v2.w, v2.w, aw);
        ax = fmaf(v3.x, v3.x, ax); ay = fmaf(v3.y, v3.y, ay);
        az = fmaf(v3.z, v3.z, az); aw = fmaf(v3.w, v3.w, aw);
        ax = fmaf(v4.x, v4.x, ax); ay = fmaf(v4.y, v4.y, ay);
        az = fmaf(v4.z, v4.z, az); aw = fmaf(v4.w, v4.w, aw);
        ax = fmaf(v5.x, v5.x, ax); ay = fmaf(v5.y, v5.y, ay);
        az = fmaf(v5.z, v5.z, az); aw = fmaf(v5.w, v5.w, aw);
        ax = fmaf(v6.x, v6.x, ax); ay = fmaf(v6.y, v6.y, ay);
        az = fmaf(v6.z, v6.z, az); aw = fmaf(v6.w, v6.w, aw);
        ax = fmaf(v7.x, v7.x, ax); ay = fmaf(v7.y, v7.y, ay);
        az = fmaf(v7.z, v7.z, az); aw = fmaf(v7.w, v7.w, aw);
    }

    // One REDG.ADD per scalar column per block (296 adds/column total).
    const int c = col4 * 4;
    atomicAdd(&g_colsum[c + 0], ax);
    atomicAdd(&g_colsum[c + 1], ay);
    atomicAdd(&g_colsum[c + 2], az);
    atomicAdd(&g_colsum[c + 3], aw);

    // Make this block's adds visible before signaling completion.
    __threadfence();

    __shared__ unsigned int s_rank;
    __syncthreads();                              // all threads' atomics issued
    if (threadIdx.x == 0) s_rank = atomicAdd(&g_done, 1u);
    __syncthreads();

    if (s_rank == GRID1 - 1) {
        // Last block: every other block's REDGs are L2-visible (they fenced
        // before bumping g_done). This block never read g_colsum, so no stale
        // L1 lines exist. Finalize in-place.
        const int t = threadIdx.x;
        const float inv_n = 1.0f / (float)N_ROWS;

        float4 sv = reinterpret_cast<const float4*>(g_colsum)[t];
        float v = fabsf(1.0f - sv.x * inv_n) + fabsf(1.0f - sv.y * inv_n)
                + fabsf(1.0f - sv.z * inv_n) + fabsf(1.0f - sv.w * inv_n);

        // Reset state for the next graph replay.
        reinterpret_cast<float4*>(g_colsum)[t] = make_float4(0.f, 0.f, 0.f, 0.f);

        __shared__ float red[16];
        #pragma unroll
        for (int o = 16; o > 0; o >>= 1)
            v += __shfl_down_sync(0xffffffff, v, o);
        if ((t & 31) == 0) red[t >> 5] = v;
        __syncthreads();
        if (t < 16) {
            float x = red[t];
            #pragma unroll
            for (int o = 8; o > 0; o >>= 1)
                x += __shfl_down_sync(0xffff, x, o);
            if (t == 0) {
                out[0] = x;
                g_done = 0;                       // reset completion counter
            }
        }
    }
}

extern "C" void kernel_launch(void* const* d_in, const int* in_sizes, int n_in,
                              void* d_out, int out_size)
{
    const float4* Y = (const float4*)d_in[0];
    float* out = (float*)d_out;

    semidef_kernel<<<GRID1, 512>>>(Y, out);
}

// round 6
// speedup vs baseline: 1.0173x; 1.0113x over previous
#include <cuda_runtime.h>

// Y: [16384, 2048] fp32, row-major.
// loss = sum_d | 1 - (sum_n Y[n,d]^2) / n |

#define N_ROWS         16384
#define N_COLS         2048
#define COLS4          (N_COLS / 4)              // 512 float4 per row
#define ROWS_PER_BLOCK 64
#define GRID1          (N_ROWS / ROWS_PER_BLOCK) // 256 blocks

// Zero-initialized device globals (no cudaMalloc allowed). The last finishing
// block reads/resets them each launch, so every graph replay starts clean.
__device__ float        g_colsum[N_COLS];
__device__ unsigned int g_done;

__global__ __launch_bounds__(512, 2) void semidef_kernel(
    const float4* __restrict__ Y, float* __restrict__ out)
{
    const int col4 = threadIdx.x;                // 0..511, fixed column group
    const long base = (long)blockIdx.x * ROWS_PER_BLOCK * COLS4 + col4;

    // Proven streaming body (R3 K1): contiguous 64-row slab per block,
    // fully unrolled so ptxas front-batches the LDG.128s (high MLP_eff).
    float ax = 0.f, ay = 0.f, az = 0.f, aw = 0.f;
    #pragma unroll
    for (int r = 0; r < ROWS_PER_BLOCK; r += 4) {
        float4 v0 = Y[base + (long)(r + 0) * COLS4];
        float4 v1 = Y[base + (long)(r + 1) * COLS4];
        float4 v2 = Y[base + (long)(r + 2) * COLS4];
        float4 v3 = Y[base + (long)(r + 3) * COLS4];
        ax = fmaf(v0.x, v0.x, ax); ay = fmaf(v0.y, v0.y, ay);
        az = fmaf(v0.z, v0.z, az); aw = fmaf(v0.w, v0.w, aw);
        ax = fmaf(v1.x, v1.x, ax); ay = fmaf(v1.y, v1.y, ay);
        az = fmaf(v1.z, v1.z, az); aw = fmaf(v1.w, v1.w, aw);
        ax = fmaf(v2.x, v2.x, ax); ay = fmaf(v2.y, v2.y, ay);
        az = fmaf(v2.z, v2.z, az); aw = fmaf(v2.w, v2.w, aw);
        ax = fmaf(v3.x, v3.x, ax); ay = fmaf(v3.y, v3.y, ay);
        az = fmaf(v3.z, v3.z, az); aw = fmaf(v3.w, v3.w, aw);
    }

    // One REDG.ADD per scalar column per block (256 adds/column total).
    const int c = col4 * 4;
    atomicAdd(&g_colsum[c + 0], ax);
    atomicAdd(&g_colsum[c + 1], ay);
    atomicAdd(&g_colsum[c + 2], az);
    atomicAdd(&g_colsum[c + 3], aw);

    // Make this block's adds visible before signaling completion.
    __threadfence();

    __shared__ unsigned int s_rank;
    __syncthreads();                              // all threads' atomics issued
    if (threadIdx.x == 0) s_rank = atomicAdd(&g_done, 1u);
    __syncthreads();

    if (s_rank == GRID1 - 1) {
        // Last block: all other blocks' REDGs are L2-visible (each fenced
        // before bumping g_done). This block never read g_colsum earlier, so
        // no stale L1 lines exist. Finalize in-place.
        const int t = threadIdx.x;
        const float inv_n = 1.0f / (float)N_ROWS;

        float4 sv = reinterpret_cast<const float4*>(g_colsum)[t];
        float v = fabsf(1.0f - sv.x * inv_n) + fabsf(1.0f - sv.y * inv_n)
                + fabsf(1.0f - sv.z * inv_n) + fabsf(1.0f - sv.w * inv_n);

        // Reset state for the next graph replay.
        reinterpret_cast<float4*>(g_colsum)[t] = make_float4(0.f, 0.f, 0.f, 0.f);

        __shared__ float red[16];
        #pragma unroll
        for (int o = 16; o > 0; o >>= 1)
            v += __shfl_down_sync(0xffffffff, v, o);
        if ((t & 31) == 0) red[t >> 5] = v;
        __syncthreads();
        if (t < 16) {
            float x = red[t];
            #pragma unroll
            for (int o = 8; o > 0; o >>= 1)
                x += __shfl_down_sync(0xffff, x, o);
            if (t == 0) {
                out[0] = x;
                g_done = 0;                       // reset completion counter
            }
        }
    }
}

extern "C" void kernel_launch(void* const* d_in, const int* in_sizes, int n_in,
                              void* d_out, int out_size)
{
    const float4* Y = (const float4*)d_in[0];
    float* out = (float*)d_out;

    semidef_kernel<<<GRID1, 512>>>(Y, out);
}

// round 7
// speedup vs baseline: 1.0182x; 1.0009x over previous
#include <cuda_runtime.h>

// Y: [16384, 2048] fp32, row-major.
// loss = sum_d | 1 - (sum_n Y[n,d]^2) / n |

#define N_ROWS         16384
#define N_COLS         2048
#define COLS4          (N_COLS / 4)              // 512 float4 per row
#define ROWS_PER_BLOCK 64
#define GRID1          (N_ROWS / ROWS_PER_BLOCK) // 256 blocks

// Zero-initialized device globals (no cudaMalloc allowed). The last finishing
// block reads/resets them each launch, so every graph replay starts clean.
__device__ float        g_colsum[N_COLS];
__device__ unsigned int g_done;

// NOTE: no min-blocks-per-SM clause — letting the register count float is what
// allows ptxas to keep 16 LDG.128 in flight (the R6 cap at 64 regs serialized
// the load batches and dropped DRAM utilization to 52%).
__global__ __launch_bounds__(512) void semidef_kernel(
    const float4* __restrict__ Y, float* __restrict__ out)
{
    const int col4 = threadIdx.x;                // 0..511, fixed column group
    const long base = (long)blockIdx.x * ROWS_PER_BLOCK * COLS4 + col4;

    // Proven streaming body (R3 K1): contiguous 64-row slab per block,
    // fully unrolled so ptxas front-batches the LDG.128s (high MLP_eff).
    float ax = 0.f, ay = 0.f, az = 0.f, aw = 0.f;
    #pragma unroll
    for (int r = 0; r < ROWS_PER_BLOCK; r += 4) {
        float4 v0 = Y[base + (long)(r + 0) * COLS4];
        float4 v1 = Y[base + (long)(r + 1) * COLS4];
        float4 v2 = Y[base + (long)(r + 2) * COLS4];
        float4 v3 = Y[base + (long)(r + 3) * COLS4];
        ax = fmaf(v0.x, v0.x, ax); ay = fmaf(v0.y, v0.y, ay);
        az = fmaf(v0.z, v0.z, az); aw = fmaf(v0.w, v0.w, aw);
        ax = fmaf(v1.x, v1.x, ax); ay = fmaf(v1.y, v1.y, ay);
        az = fmaf(v1.z, v1.z, az); aw = fmaf(v1.w, v1.w, aw);
        ax = fmaf(v2.x, v2.x, ax); ay = fmaf(v2.y, v2.y, ay);
        az = fmaf(v2.z, v2.z, az); aw = fmaf(v2.w, v2.w, aw);
        ax = fmaf(v3.x, v3.x, ax); ay = fmaf(v3.y, v3.y, ay);
        az = fmaf(v3.z, v3.z, az); aw = fmaf(v3.w, v3.w, aw);
    }

    // One REDG.ADD per scalar column per block (256 adds/column total).
    const int c = col4 * 4;
    atomicAdd(&g_colsum[c + 0], ax);
    atomicAdd(&g_colsum[c + 1], ay);
    atomicAdd(&g_colsum[c + 2], az);
    atomicAdd(&g_colsum[c + 3], aw);

    // Make this block's adds visible before signaling completion.
    __threadfence();

    __shared__ unsigned int s_rank;
    __syncthreads();                              // all threads' atomics issued
    if (threadIdx.x == 0) s_rank = atomicAdd(&g_done, 1u);
    __syncthreads();

    if (s_rank == GRID1 - 1) {
        // Last block: all other blocks' REDGs are L2-visible (each fenced
        // before bumping g_done). This block never read g_colsum earlier, so
        // no stale L1 lines exist. Finalize in-place.
        const int t = threadIdx.x;
        const float inv_n = 1.0f / (float)N_ROWS;

        float4 sv = reinterpret_cast<const float4*>(g_colsum)[t];
        float v = fabsf(1.0f - sv.x * inv_n) + fabsf(1.0f - sv.y * inv_n)
                + fabsf(1.0f - sv.z * inv_n) + fabsf(1.0f - sv.w * inv_n);

        // Reset state for the next graph replay.
        reinterpret_cast<float4*>(g_colsum)[t] = make_float4(0.f, 0.f, 0.f, 0.f);

        __shared__ float red[16];
        #pragma unroll
        for (int o = 16; o > 0; o >>= 1)
            v += __shfl_down_sync(0xffffffff, v, o);
        if ((t & 31) == 0) red[t >> 5] = v;
        __syncthreads();
        if (t < 16) {
            float x = red[t];
            #pragma unroll
            for (int o = 8; o > 0; o >>= 1)
                x += __shfl_down_sync(0xffff, x, o);
            if (t == 0) {
                out[0] = x;
                g_done = 0;                       // reset completion counter
            }
        }
    }
}

extern "C" void kernel_launch(void* const* d_in, const int* in_sizes, int n_in,
                              void* d_out, int out_size)
{
    const float4* Y = (const float4*)d_in[0];
    float* out = (float*)d_out;

    semidef_kernel<<<GRID1, 512>>>(Y, out);
}